// round 2
// baseline (speedup 1.0000x reference)
#include <cuda_runtime.h>
#include <cuda_bf16.h>

#define FIELDS 39
#define DIM    16
#define CROSS  741   // 39*38/2
#define TPB    256

// Pair index table: packed (i<<8)|j for pair p in the reference's
// row-major upper-triangle order. Filled by an init kernel every launch
// (deterministic + graph-capturable; no device allocation).
__device__ unsigned short g_pair[CROSS];

__global__ void fwfm_init_pairs()
{
    int p = blockIdx.x * blockDim.x + threadIdx.x;
    if (p >= CROSS) return;
    int i = 0, rem = p, cnt = FIELDS - 1;
    while (rem >= cnt) { rem -= cnt; cnt--; i++; }
    int j = i + 1 + rem;
    g_pair[p] = (unsigned short)((i << 8) | j);
}

__global__ __launch_bounds__(TPB)
void fwfm_kernel(const int*   __restrict__ inputs,     // [B, 39]
                 const float* __restrict__ emb,        // [1e6, 16]
                 const float* __restrict__ fw,         // [741, 1]
                 const float* __restrict__ lw,         // [1e6]
                 const float* __restrict__ bias,       // scalar
                 float*       __restrict__ out)        // [B, 1]
{
    __shared__ float s_emb[FIELDS][DIM];   // 39*16*4 = 2496 B
    __shared__ int   s_idx[FIELDS];
    __shared__ float s_red[TPB / 32];

    const int b = blockIdx.x;
    const int t = threadIdx.x;

    // stage feature ids
    if (t < FIELDS) s_idx[t] = inputs[b * FIELDS + t];
    __syncthreads();

    // gather 39 embedding rows as float4 (156 independent loads -> high MLP)
    if (t < FIELDS * 4) {
        const int f = t >> 2, c = t & 3;
        const float4 v =
            reinterpret_cast<const float4*>(emb + (size_t)s_idx[f] * DIM)[c];
        reinterpret_cast<float4*>(&s_emb[f][0])[c] = v;
    }

    // first-order term: one gathered weight per field
    float acc = 0.0f;
    if (t < FIELDS) acc = lw[s_idx[t]];

    __syncthreads();

    // second-order: 741 weighted pair dots, strided across the block
    for (int p = t; p < CROSS; p += TPB) {
        const int pk = g_pair[p];
        const int i = pk >> 8;
        const int j = pk & 0xFF;
        float dot = 0.0f;
#pragma unroll
        for (int d = 0; d < DIM; d++)
            dot = fmaf(s_emb[i][d], s_emb[j][d], dot);
        acc = fmaf(dot, fw[p], acc);
    }

    // block reduce
#pragma unroll
    for (int o = 16; o > 0; o >>= 1)
        acc += __shfl_down_sync(0xffffffffu, acc, o);
    if ((t & 31) == 0) s_red[t >> 5] = acc;
    __syncthreads();

    if (t < TPB / 32) {
        float v = s_red[t];
#pragma unroll
        for (int o = (TPB / 32) >> 1; o > 0; o >>= 1)
            v += __shfl_down_sync(0xffu, v, o, TPB / 32);
        if (t == 0) out[b] = v + bias[0];
    }
}

extern "C" void kernel_launch(void* const* d_in, const int* in_sizes, int n_in,
                              void* d_out, int out_size)
{
    const int*   inputs = (const int*)  d_in[0];
    const float* emb    = (const float*)d_in[1];
    const float* fw     = (const float*)d_in[2];
    const float* lw     = (const float*)d_in[3];
    const float* bias   = (const float*)d_in[4];
    float*       out    = (float*)d_out;

    const int batch = in_sizes[0] / FIELDS;

    fwfm_init_pairs<<<(CROSS + TPB - 1) / TPB, TPB>>>();
    fwfm_kernel<<<batch, TPB>>>(inputs, emb, fw, lw, bias, out);
}

// round 6
// speedup vs baseline: 2.6045x; 2.6045x over previous
#include <cuda_runtime.h>
#include <cuda_bf16.h>

#define FIELDS 39
#define DIM    16
#define SPAD   17     // padded smem row stride (odd -> conflict-free banks)
#define CROSS  741    // 39*38/2
#define TPB    256

// Pair index table: packed (i<<8)|j for pair p in the reference's
// row-major upper-triangle order. Filled by an init kernel every launch
// (deterministic + graph-capturable; no device allocation).
__device__ unsigned short g_pair[CROSS];

__global__ void fwfm_init_pairs()
{
    int p = blockIdx.x * blockDim.x + threadIdx.x;
    if (p >= CROSS) return;
    int i = 0, rem = p, cnt = FIELDS - 1;
    while (rem >= cnt) { rem -= cnt; cnt--; i++; }
    int j = i + 1 + rem;
    g_pair[p] = (unsigned short)((i << 8) | j);
}

__global__ __launch_bounds__(TPB)
void fwfm_kernel(const int*   __restrict__ inputs,     // [B, 39]
                 const float* __restrict__ emb,        // [1e6, 16]
                 const float* __restrict__ fw,         // [741, 1]
                 const float* __restrict__ lw,         // [1e6]
                 const float* __restrict__ bias,       // scalar
                 float*       __restrict__ out)        // [B, 1]
{
    __shared__ float s_emb[FIELDS][SPAD];  // stride 17 -> conflict-free
    __shared__ int   s_idx[FIELDS];
    __shared__ float s_red[TPB / 32];

    const int b = blockIdx.x;
    const int t = threadIdx.x;

    // stage feature ids
    if (t < FIELDS) s_idx[t] = inputs[b * FIELDS + t];
    __syncthreads();

    // gather 39 embedding rows as float4 (156 independent loads -> high MLP)
    if (t < FIELDS * 4) {
        const int f = t >> 2, c = t & 3;
        const float4 v =
            reinterpret_cast<const float4*>(emb + (size_t)s_idx[f] * DIM)[c];
        s_emb[f][4 * c + 0] = v.x;
        s_emb[f][4 * c + 1] = v.y;
        s_emb[f][4 * c + 2] = v.z;
        s_emb[f][4 * c + 3] = v.w;
    }

    // first-order term: one gathered weight per field
    float acc = 0.0f;
    if (t < FIELDS) acc = lw[s_idx[t]];

    __syncthreads();

    // second-order: 741 weighted pair dots, strided across the block
    for (int p = t; p < CROSS; p += TPB) {
        const int pk = g_pair[p];
        const int i = pk >> 8;
        const int j = pk & 0xFF;
        float dot = 0.0f;
#pragma unroll
        for (int d = 0; d < DIM; d++)
            dot = fmaf(s_emb[i][d], s_emb[j][d], dot);
        acc = fmaf(dot, fw[p], acc);
    }

    // block reduce
#pragma unroll
    for (int o = 16; o > 0; o >>= 1)
        acc += __shfl_down_sync(0xffffffffu, acc, o);
    if ((t & 31) == 0) s_red[t >> 5] = acc;
    __syncthreads();

    if (t < TPB / 32) {
        float v = s_red[t];
#pragma unroll
        for (int o = (TPB / 32) >> 1; o > 0; o >>= 1)
            v += __shfl_down_sync(0xffu, v, o, TPB / 32);
        if (t == 0) out[b] = v + bias[0];
    }
}

extern "C" void kernel_launch(void* const* d_in, const int* in_sizes, int n_in,
                              void* d_out, int out_size)
{
    const int*   inputs = (const int*)  d_in[0];
    const float* emb    = (const float*)d_in[1];
    const float* fw     = (const float*)d_in[2];
    const float* lw     = (const float*)d_in[3];
    const float* bias   = (const float*)d_in[4];
    float*       out    = (float*)d_out;

    const int batch = in_sizes[0] / FIELDS;

    fwfm_init_pairs<<<(CROSS + TPB - 1) / TPB, TPB>>>();
    fwfm_kernel<<<batch, TPB>>>(inputs, emb, fw, lw, bias, out);
}